// round 8
// baseline (speedup 1.0000x reference)
#include <cuda_runtime.h>
#include <cuda_bf16.h>

// Problem shape (fixed by reference setup_inputs)
#define NB 4
#define NH 16
#define SQ 2048
#define HD 4
#define WPB 16          // warps per block
#define QPB 8           // queries per block (share K/V)
#define KPL 4           // keys per lane (stride-32 in warp's 128-key slice)

typedef unsigned long long u64;

__device__ __forceinline__ float ex2(float x) {
    float r; asm("ex2.approx.f32 %0, %1;" : "=f"(r) : "f"(x)); return r;
}
__device__ __forceinline__ u64 pk(float a, float b) {
    u64 r; asm("mov.b64 %0, {%1, %2};" : "=l"(r) : "f"(a), "f"(b)); return r;
}
__device__ __forceinline__ u64 dup(float a) {
    u64 r; asm("mov.b64 %0, {%1, %1};" : "=l"(r) : "f"(a)); return r;
}
__device__ __forceinline__ void upk(u64 v, float& a, float& b) {
    asm("mov.b64 {%0, %1}, %2;" : "=f"(a), "=f"(b) : "l"(v));
}
__device__ __forceinline__ u64 mul2(u64 a, u64 b) {
    u64 r; asm("mul.rn.f32x2 %0, %1, %2;" : "=l"(r) : "l"(a), "l"(b)); return r;
}
__device__ __forceinline__ u64 fma2(u64 a, u64 b, u64 c) {
    u64 r; asm("fma.rn.f32x2 %0, %1, %2, %3;" : "=l"(r) : "l"(a), "l"(b), "l"(c)); return r;
}
__device__ __forceinline__ u64 add2(u64 a, u64 b) {
    u64 r; asm("add.rn.f32x2 %0, %1, %2;" : "=l"(r) : "l"(a), "l"(b)); return r;
}
// butterfly-reduce a packed f32x2 pair across the warp (2 SHFL + 1 packed add per step)
__device__ __forceinline__ u64 wredux2(u64 v) {
    float a, b; upk(v, a, b);
    #pragma unroll
    for (int off = 16; off; off >>= 1) {
        const float a2 = __shfl_xor_sync(0xffffffffu, a, off);
        const float b2 = __shfl_xor_sync(0xffffffffu, b, off);
        u64 s = add2(pk(a, b), pk(a2, b2));
        upk(s, a, b);
    }
    return pk(a, b);
}

__device__ float g_scratch_out[(size_t)NB * NH * SQ * HD];

__global__ __launch_bounds__(WPB * 32, 1)
void mha_fwd_kernel(const float* __restrict__ Q,
                    const float* __restrict__ K,
                    const float* __restrict__ V,
                    const int*   __restrict__ M,
                    float* __restrict__ Out,
                    float* __restrict__ Attn,
                    int writeAttn)
{
    const int lane = threadIdx.x & 31;
    const int warp = threadIdx.x >> 5;
    const int q0g  = blockIdx.x * QPB;          // base query in B*H*S space
    const int bh   = q0g >> 11;
    const int b    = bh >> 4;
    const int qi0  = q0g & (SQ - 1);

    const float4* __restrict__ Kv = (const float4*)K + (size_t)bh * SQ;
    const float4* __restrict__ Vv = (const float4*)V + (size_t)bh * SQ;
    const int*    __restrict__ Mb = M + ((size_t)b * SQ + qi0) * SQ;
    float* __restrict__ Ab = Attn + (size_t)q0g * SQ;   // valid only if writeAttn

    // q pre-scaled by 0.5*log2(e), packed as query-pairs per component
    const float c = 0.72134752044448169f;
    u64 qpx[4], qpy[4], qpz[4], qpw[4];
    #pragma unroll
    for (int pp = 0; pp < 4; pp++) {
        float4 a = ((const float4*)Q)[q0g + 2*pp + 0];
        float4 d = ((const float4*)Q)[q0g + 2*pp + 1];
        qpx[pp] = pk(a.x * c, d.x * c);
        qpy[pp] = pk(a.y * c, d.y * c);
        qpz[pp] = pk(a.z * c, d.z * c);
        qpw[pp] = pk(a.w * c, d.w * c);
    }

    __shared__ float part1[WPB][QPB];        // row sums
    __shared__ float part2[WPB][QPB][4];     // out partials
    __shared__ float sinv[QPB];
    __shared__ int   sflag[QPB];

    // ---- Pass 1: p = masked exp(score); per-query sums ----
    float p[QPB][KPL];
    u64 psum[4];
    #pragma unroll
    for (int pp = 0; pp < 4; pp++) psum[pp] = 0;

    const int kbase = warp * (SQ / WPB) + lane;   // warp owns 128 keys, lane stride 32

    #pragma unroll
    for (int u = 0; u < KPL; u++) {
        const int kk = kbase + u * 32;
        const float4 k = Kv[kk];
        int m[QPB];
        #pragma unroll
        for (int q = 0; q < QPB; q++) m[q] = Mb[q * SQ + kk];   // const-offset LDGs

        const u64 kxx = dup(k.x), kyy = dup(k.y), kzz = dup(k.z), kww = dup(k.w);

        #pragma unroll
        for (int pp = 0; pp < 4; pp++) {
            u64 s01 = mul2(qpx[pp], kxx);
            s01 = fma2(qpy[pp], kyy, s01);
            s01 = fma2(qpz[pp], kzz, s01);
            s01 = fma2(qpw[pp], kww, s01);
            float sa, sb; upk(s01, sa, sb);
            const float pa = m[2*pp+0] ? ex2(sa) : 0.f;
            const float pb = m[2*pp+1] ? ex2(sb) : 0.f;
            psum[pp] = add2(psum[pp], pk(pa, pb));
            p[2*pp+0][u] = pa;  p[2*pp+1][u] = pb;
        }
    }

    #pragma unroll
    for (int pp = 0; pp < 4; pp++) {
        const u64 s = wredux2(psum[pp]);
        if (lane == 0) {
            float a, b; upk(s, a, b);
            part1[warp][2*pp+0] = a; part1[warp][2*pp+1] = b;
        }
    }
    __syncthreads();

    if (threadIdx.x < QPB) {
        const int q = threadIdx.x;
        float s = 0.f;
        #pragma unroll
        for (int wp = 0; wp < WPB; wp++) s += part1[wp][q];
        const int flag = (s == 0.f);             // all-masked -> uniform softmax
        sinv[q]  = 1.0f / (flag ? (float)SQ : s);
        sflag[q] = flag;
    }
    __syncthreads();

    float inv[QPB];
    #pragma unroll
    for (int q = 0; q < QPB; q++) {
        inv[q] = sinv[q];
        if (sflag[q]) {                          // uniform row: p := 1
            #pragma unroll
            for (int u = 0; u < KPL; u++) p[q][u] = 1.f;
        }
    }

    // ---- Pass 2: normalize, store attn, accumulate out (packed f32x2) ----
    u64 accx[4], accy[4], accz[4], accw[4];
    #pragma unroll
    for (int pp = 0; pp < 4; pp++) { accx[pp]=0; accy[pp]=0; accz[pp]=0; accw[pp]=0; }

    #pragma unroll
    for (int u = 0; u < KPL; u++) {
        const int kk = kbase + u * 32;
        const float4 v = Vv[kk];
        const u64 vxx = dup(v.x), vyy = dup(v.y), vzz = dup(v.z), vww = dup(v.w);

        #pragma unroll
        for (int pp = 0; pp < 4; pp++) {
            const float na = p[2*pp+0][u] * inv[2*pp+0];
            const float nb = p[2*pp+1][u] * inv[2*pp+1];
            if (writeAttn) {
                __stcs(Ab + (size_t)(2*pp+0) * SQ + kk, na);
                __stcs(Ab + (size_t)(2*pp+1) * SQ + kk, nb);
            }
            const u64 n01 = pk(na, nb);
            accx[pp] = fma2(n01, vxx, accx[pp]);
            accy[pp] = fma2(n01, vyy, accy[pp]);
            accz[pp] = fma2(n01, vzz, accz[pp]);
            accw[pp] = fma2(n01, vww, accw[pp]);
        }
    }

    #pragma unroll
    for (int pp = 0; pp < 4; pp++) {
        const u64 rx = wredux2(accx[pp]);
        const u64 ry = wredux2(accy[pp]);
        const u64 rz = wredux2(accz[pp]);
        const u64 rw = wredux2(accw[pp]);
        if (lane == 0) {
            float xa, xb, ya, yb, za, zb, wa, wb;
            upk(rx, xa, xb); upk(ry, ya, yb); upk(rz, za, zb); upk(rw, wa, wb);
            part2[warp][2*pp+0][0]=xa; part2[warp][2*pp+0][1]=ya;
            part2[warp][2*pp+0][2]=za; part2[warp][2*pp+0][3]=wa;
            part2[warp][2*pp+1][0]=xb; part2[warp][2*pp+1][1]=yb;
            part2[warp][2*pp+1][2]=zb; part2[warp][2*pp+1][3]=wb;
        }
    }
    __syncthreads();

    if (threadIdx.x < QPB) {
        const int q = threadIdx.x;
        float x=0.f, y=0.f, z=0.f, w=0.f;
        #pragma unroll
        for (int wp = 0; wp < WPB; wp++) {
            x += part2[wp][q][0]; y += part2[wp][q][1];
            z += part2[wp][q][2]; w += part2[wp][q][3];
        }
        ((float4*)Out)[q0g + q] = make_float4(x, y, z, w);
    }
}

extern "C" void kernel_launch(void* const* d_in, const int* in_sizes, int n_in,
                              void* d_out, int out_size)
{
    const float* Q = (const float*)d_in[0];
    const float* K = (const float*)d_in[1];
    const float* V = (const float*)d_in[2];
    const int*   M = (const int*)d_in[3];

    const long long outE  = (long long)NB * NH * SQ * HD;   //    524,288
    const long long attnE = (long long)NB * NH * SQ * SQ;   // 268,435,456

    float* Out  = nullptr;
    float* Attn = nullptr;
    int writeAttn = 0;

    const long long osz = (long long)out_size;
    if (osz >= outE + attnE) {
        Out  = (float*)d_out;           // tuple (out, attn) flattened in order
        Attn = (float*)d_out + outE;
        writeAttn = 1;
    } else if (osz == attnE) {
        Attn = (float*)d_out;
        writeAttn = 1;
        Out = g_scratch_out;
    } else {
        Out = (float*)d_out;
        writeAttn = 0;
        Attn = (float*)d_out;           // unused (guarded by writeAttn)
    }

    const int blocks = (NB * NH * SQ) / QPB;   // 16384
    mha_fwd_kernel<<<blocks, WPB * 32>>>(Q, K, V, M, Out, Attn, writeAttn);
}

// round 11
// speedup vs baseline: 1.7465x; 1.7465x over previous
#include <cuda_runtime.h>
#include <cuda_fp16.h>

// Problem shape (fixed by reference setup_inputs)
#define NB 4
#define NH 16
#define SQ 2048
#define HD 4
#define WPB 8           // warps per block
#define QPB 4           // queries per block (share K/V)
#define KPL 8           // keys per lane (stride-32 in warp's 256-key slice)

typedef unsigned long long u64;

__device__ __forceinline__ float ex2(float x) {
    float r; asm("ex2.approx.f32 %0, %1;" : "=f"(r) : "f"(x)); return r;
}
__device__ __forceinline__ u64 pk(float a, float b) {
    u64 r; asm("mov.b64 %0, {%1, %2};" : "=l"(r) : "f"(a), "f"(b)); return r;
}
__device__ __forceinline__ u64 dup(float a) {
    u64 r; asm("mov.b64 %0, {%1, %1};" : "=l"(r) : "f"(a)); return r;
}
__device__ __forceinline__ void upk(u64 v, float& a, float& b) {
    asm("mov.b64 {%0, %1}, %2;" : "=f"(a), "=f"(b) : "l"(v));
}
__device__ __forceinline__ u64 mul2(u64 a, u64 b) {
    u64 r; asm("mul.rn.f32x2 %0, %1, %2;" : "=l"(r) : "l"(a), "l"(b)); return r;
}
__device__ __forceinline__ u64 fma2(u64 a, u64 b, u64 c) {
    u64 r; asm("fma.rn.f32x2 %0, %1, %2, %3;" : "=l"(r) : "l"(a), "l"(b), "l"(c)); return r;
}
__device__ __forceinline__ u64 add2(u64 a, u64 b) {
    u64 r; asm("add.rn.f32x2 %0, %1, %2;" : "=l"(r) : "l"(a), "l"(b)); return r;
}
// butterfly-reduce a packed f32x2 pair across the warp
__device__ __forceinline__ u64 wredux2(u64 v) {
    float a, b; upk(v, a, b);
    #pragma unroll
    for (int off = 16; off; off >>= 1) {
        const float a2 = __shfl_xor_sync(0xffffffffu, a, off);
        const float b2 = __shfl_xor_sync(0xffffffffu, b, off);
        u64 s = add2(pk(a, b), pk(a2, b2));
        upk(s, a, b);
    }
    return pk(a, b);
}

__device__ float g_scratch_out[(size_t)NB * NH * SQ * HD];

__global__ __launch_bounds__(WPB * 32, 4)
void mha_fwd_kernel(const float* __restrict__ Q,
                    const float* __restrict__ K,
                    const float* __restrict__ V,
                    const int*   __restrict__ M,
                    float* __restrict__ Out,
                    float* __restrict__ Attn,
                    int writeAttn)
{
    const int lane = threadIdx.x & 31;
    const int warp = threadIdx.x >> 5;
    const int q0g  = blockIdx.x * QPB;          // base query in B*H*S space
    const int bh   = q0g >> 11;
    const int b    = bh >> 4;
    const int qi0  = q0g & (SQ - 1);

    const float4* __restrict__ Kv = (const float4*)K + (size_t)bh * SQ;
    const float4* __restrict__ Vv = (const float4*)V + (size_t)bh * SQ;
    const int*    __restrict__ Mb = M + ((size_t)b * SQ + qi0) * SQ;
    float* __restrict__ Ab = Attn + (size_t)q0g * SQ;   // valid only if writeAttn

    // q pre-scaled by 0.5*log2(e), packed as 2 query-pairs per component.
    // ex2(dot(qc,k) - 6) = exp(score) * 2^-6 -> fp16-safe (tail score <= ~12).
    // The 2^-6 cancels in normalization because sums accumulate scaled values.
    const float c = 0.72134752044448169f;
    const u64 BIAS = pk(-6.0f, -6.0f);
    u64 qpx[2], qpy[2], qpz[2], qpw[2];
    #pragma unroll
    for (int pp = 0; pp < 2; pp++) {
        float4 a = ((const float4*)Q)[q0g + 2*pp + 0];
        float4 d = ((const float4*)Q)[q0g + 2*pp + 1];
        qpx[pp] = pk(a.x * c, d.x * c);
        qpy[pp] = pk(a.y * c, d.y * c);
        qpz[pp] = pk(a.z * c, d.z * c);
        qpw[pp] = pk(a.w * c, d.w * c);
    }

    __shared__ float part1[WPB][QPB];        // row sums (of scaled p)
    __shared__ float part2[WPB][QPB][4];     // out partials
    __shared__ float sinv[QPB];
    __shared__ int   sflag[QPB];

    // ---- Pass 1: p' = masked exp(score)*2^-6; per-query sums (scaled).
    //      p' stored as half2 per query-pair (register savings -> occupancy). ----
    __half2 p2[2][KPL];
    u64 psum[2];
    psum[0] = 0; psum[1] = 0;

    const int kbase = warp * (SQ / WPB) + lane;   // warp owns 256 keys, lane stride 32

    #pragma unroll
    for (int u = 0; u < KPL; u++) {
        const int kk = kbase + u * 32;
        const float4 k = Kv[kk];
        const int m0 = Mb[0 * SQ + kk];
        const int m1 = Mb[1 * SQ + kk];
        const int m2 = Mb[2 * SQ + kk];
        const int m3 = Mb[3 * SQ + kk];

        const u64 kxx = dup(k.x), kyy = dup(k.y), kzz = dup(k.z), kww = dup(k.w);

        u64 s01 = fma2(qpx[0], kxx, BIAS);
        s01 = fma2(qpy[0], kyy, s01);
        s01 = fma2(qpz[0], kzz, s01);
        s01 = fma2(qpw[0], kww, s01);
        u64 s23 = fma2(qpx[1], kxx, BIAS);
        s23 = fma2(qpy[1], kyy, s23);
        s23 = fma2(qpz[1], kzz, s23);
        s23 = fma2(qpw[1], kww, s23);

        float sa, sb, sc2, sd; upk(s01, sa, sb); upk(s23, sc2, sd);
        const float pa = m0 ? ex2(sa)  : 0.f;
        const float pb = m1 ? ex2(sb)  : 0.f;
        const float pc = m2 ? ex2(sc2) : 0.f;
        const float pd = m3 ? ex2(sd)  : 0.f;

        psum[0] = add2(psum[0], pk(pa, pb));
        psum[1] = add2(psum[1], pk(pc, pd));
        p2[0][u] = __floats2half2_rn(pa, pb);
        p2[1][u] = __floats2half2_rn(pc, pd);
    }

    #pragma unroll
    for (int pp = 0; pp < 2; pp++) {
        const u64 s = wredux2(psum[pp]);
        if (lane == 0) {
            float a, bb; upk(s, a, bb);
            part1[warp][2*pp+0] = a; part1[warp][2*pp+1] = bb;
        }
    }
    __syncthreads();

    if (threadIdx.x < QPB) {
        const int q = threadIdx.x;
        float s = 0.f;
        #pragma unroll
        for (int wp = 0; wp < WPB; wp++) s += part1[wp][q];
        const int flag = (s == 0.f);             // all-masked -> uniform softmax
        sinv[q]  = 1.0f / (flag ? (float)SQ : s);
        sflag[q] = flag;
    }
    __syncthreads();

    u64 inv01 = pk(sinv[0], sinv[1]);
    u64 inv23 = pk(sinv[2], sinv[3]);
    {
        // uniform rows: p := 1 (ratio 1/SQ after normalization)
        const __half2 one2 = __floats2half2_rn(1.f, 1.f);
        if (sflag[0] | sflag[1]) {
            #pragma unroll
            for (int u = 0; u < KPL; u++) {
                __half2 t = p2[0][u];
                if (sflag[0]) t.x = one2.x;
                if (sflag[1]) t.y = one2.y;
                p2[0][u] = t;
            }
        }
        if (sflag[2] | sflag[3]) {
            #pragma unroll
            for (int u = 0; u < KPL; u++) {
                __half2 t = p2[1][u];
                if (sflag[2]) t.x = one2.x;
                if (sflag[3]) t.y = one2.y;
                p2[1][u] = t;
            }
        }
    }

    // ---- Pass 2: normalize, store attn (evict-first), accumulate out ----
    u64 accx[2], accy[2], accz[2], accw[2];
    #pragma unroll
    for (int pp = 0; pp < 2; pp++) { accx[pp]=0; accy[pp]=0; accz[pp]=0; accw[pp]=0; }

    #pragma unroll
    for (int u = 0; u < KPL; u++) {
        const int kk = kbase + u * 32;
        const float4 v = Vv[kk];
        const u64 vxx = dup(v.x), vyy = dup(v.y), vzz = dup(v.z), vww = dup(v.w);

        const float2 f01 = __half22float2(p2[0][u]);
        const float2 f23 = __half22float2(p2[1][u]);
        const u64 n01 = mul2(pk(f01.x, f01.y), inv01);
        const u64 n23 = mul2(pk(f23.x, f23.y), inv23);

        if (writeAttn) {
            float na, nb, nc, nd;
            upk(n01, na, nb); upk(n23, nc, nd);
            __stcs(Ab + (size_t)0 * SQ + kk, na);
            __stcs(Ab + (size_t)1 * SQ + kk, nb);
            __stcs(Ab + (size_t)2 * SQ + kk, nc);
            __stcs(Ab + (size_t)3 * SQ + kk, nd);
        }

        accx[0] = fma2(n01, vxx, accx[0]);  accx[1] = fma2(n23, vxx, accx[1]);
        accy[0] = fma2(n01, vyy, accy[0]);  accy[1] = fma2(n23, vyy, accy[1]);
        accz[0] = fma2(n01, vzz, accz[0]);  accz[1] = fma2(n23, vzz, accz[1]);
        accw[0] = fma2(n01, vww, accw[0]);  accw[1] = fma2(n23, vww, accw[1]);
    }

    #pragma unroll
    for (int pp = 0; pp < 2; pp++) {
        const u64 rx = wredux2(accx[pp]);
        const u64 ry = wredux2(accy[pp]);
        const u64 rz = wredux2(accz[pp]);
        const u64 rw = wredux2(accw[pp]);
        if (lane == 0) {
            float xa, xb, ya, yb, za, zb, wa, wb;
            upk(rx, xa, xb); upk(ry, ya, yb); upk(rz, za, zb); upk(rw, wa, wb);
            part2[warp][2*pp+0][0]=xa; part2[warp][2*pp+0][1]=ya;
            part2[warp][2*pp+0][2]=za; part2[warp][2*pp+0][3]=wa;
            part2[warp][2*pp+1][0]=xb; part2[warp][2*pp+1][1]=yb;
            part2[warp][2*pp+1][2]=zb; part2[warp][2*pp+1][3]=wb;
        }
    }
    __syncthreads();

    if (threadIdx.x < QPB) {
        const int q = threadIdx.x;
        float x=0.f, y=0.f, z=0.f, w=0.f;
        #pragma unroll
        for (int wp = 0; wp < WPB; wp++) {
            x += part2[wp][q][0]; y += part2[wp][q][1];
            z += part2[wp][q][2]; w += part2[wp][q][3];
        }
        ((float4*)Out)[q0g + q] = make_float4(x, y, z, w);
    }
}

extern "C" void kernel_launch(void* const* d_in, const int* in_sizes, int n_in,
                              void* d_out, int out_size)
{
    const float* Q = (const float*)d_in[0];
    const float* K = (const float*)d_in[1];
    const float* V = (const float*)d_in[2];
    const int*   M = (const int*)d_in[3];

    const long long outE  = (long long)NB * NH * SQ * HD;   //    524,288
    const long long attnE = (long long)NB * NH * SQ * SQ;   // 268,435,456

    float* Out  = nullptr;
    float* Attn = nullptr;
    int writeAttn = 0;

    const long long osz = (long long)out_size;
    if (osz >= outE + attnE) {
        Out  = (float*)d_out;           // tuple (out, attn) flattened in order
        Attn = (float*)d_out + outE;
        writeAttn = 1;
    } else if (osz == attnE) {
        Attn = (float*)d_out;
        writeAttn = 1;
        Out = g_scratch_out;
    } else {
        Out = (float*)d_out;
        writeAttn = 0;
        Attn = (float*)d_out;           // unused (guarded by writeAttn)
    }

    const int blocks = (NB * NH * SQ) / QPB;   // 32768
    mha_fwd_kernel<<<blocks, WPB * 32>>>(Q, K, V, M, Out, Attn, writeAttn);
}